// round 11
// baseline (speedup 1.0000x reference)
#include <cuda_runtime.h>
#include <cuda_fp16.h>
#include <math.h>
#include <stdint.h>

// ---------------------------------------------------------------------------
// Problem constants
// ---------------------------------------------------------------------------
#define M_TOK   11520
#define DIM     512
#define HID     1960
#define BPRIME  16
#define NCH     40
#define OH      20
#define OW      36
#define LVEC    720
#define HP      66
#define WP      114
#define NPIX    (BPRIME*NCH*HP*WP)

#define N1PAD   2048
#define K2PAD   1984

// Scratch
__device__ __half g_h   [(size_t)M_TOK * HID];
__device__ __half g_pix [(size_t)NPIX];
__device__ __half g_A1  [(size_t)M_TOK * DIM];
__device__ __half g_B1  [(size_t)N1PAD * DIM];
__device__ __half g_A2  [(size_t)M_TOK * K2PAD];
__device__ __half g_B2  [(size_t)DIM   * K2PAD];
__device__ float  g_part[2][(size_t)M_TOK * DIM];

__device__ __forceinline__ float gelu_exact(float v) {
    return 0.5f * v * (1.0f + erff(v * 0.70710678118654752f));
}

// ---------------------------------------------------------------------------
// operand prep kernels (vectorized)
// ---------------------------------------------------------------------------
__global__ void prep_x_kernel(const float4* __restrict__ x, __half2* __restrict__ A1)
{
    int idx = blockIdx.x * blockDim.x + threadIdx.x;
    if (idx >= M_TOK * DIM / 4) return;
    float4 v = x[idx];
    A1[idx * 2 + 0] = __floats2half2_rn(v.x, v.y);
    A1[idx * 2 + 1] = __floats2half2_rn(v.z, v.w);
}

__global__ void prep_W1_kernel(const float* __restrict__ W1, __half2* __restrict__ B1)
{
    int idx = blockIdx.x * blockDim.x + threadIdx.x;
    if (idx >= N1PAD * DIM / 4) return;
    int n = (idx * 4) / DIM;
    float4 v = make_float4(0.f, 0.f, 0.f, 0.f);
    if (n < HID) v = *reinterpret_cast<const float4*>(W1 + (size_t)idx * 4);
    B1[idx * 2 + 0] = __floats2half2_rn(v.x, v.y);
    B1[idx * 2 + 1] = __floats2half2_rn(v.z, v.w);
}

__global__ void prep_W2_kernel(const float* __restrict__ W2, __half2* __restrict__ B2)
{
    int idx = blockIdx.x * blockDim.x + threadIdx.x;
    if (idx >= DIM * K2PAD / 4) return;
    int n  = (idx * 4) / K2PAD;
    int j  = (idx * 4) - n * K2PAD;
    float4 v = make_float4(0.f, 0.f, 0.f, 0.f);
    if (j < HID) v = *reinterpret_cast<const float4*>(W2 + (size_t)n * HID + j);
    B2[idx * 2 + 0] = __floats2half2_rn(v.x, v.y);
    B2[idx * 2 + 1] = __floats2half2_rn(v.z, v.w);
}

// ---------------------------------------------------------------------------
// fold + normalize + border-mask (gather, no atomics), fp16 in/out
// ---------------------------------------------------------------------------
__global__ void fold_div_kernel(const __half* __restrict__ h, __half* __restrict__ pix)
{
    int idx = blockIdx.x * blockDim.x + threadIdx.x;
    if (idx >= NPIX) return;
    int ix = idx % WP;
    int t  = idx / WP;
    int iy = t % HP;  t /= HP;
    int c  = t % NCH;
    int b  = t / NCH;

    float val = 0.0f;
    if (iy >= 3 && iy < 63 && ix >= 3 && ix < 111) {
        int oy_lo = max(0, (iy - 4) / 3);
        int oy_hi = min(OH - 1, iy / 3);
        int ox_lo = max(0, (ix - 4) / 3);
        int ox_hi = min(OW - 1, ix / 3);
        int cnt = (oy_hi - oy_lo + 1) * (ox_hi - ox_lo + 1);
        float acc = 0.0f;
        for (int oy = oy_lo; oy <= oy_hi; oy++) {
            int kh = iy - 3 * oy;
            for (int ox = ox_lo; ox <= ox_hi; ox++) {
                int kw = ix - 3 * ox;
                int token = b * LVEC + oy * OW + ox;
                acc += __half2float(h[(size_t)token * HID + c * 49 + kh * 7 + kw]);
            }
        }
        val = acc / (float)cnt;
    }
    pix[idx] = __float2half(val);
}

// unfold + GELU -> fp16 A2 (half2)
__global__ void prep_A2_kernel(const __half* __restrict__ pix, __half2* __restrict__ A2)
{
    int idx = blockIdx.x * blockDim.x + threadIdx.x;
    if (idx >= M_TOK * (K2PAD / 2)) return;
    int token = idx / (K2PAD / 2);
    int j0    = (idx - token * (K2PAD / 2)) * 2;
    int b  = token / LVEC;
    int l  = token - b * LVEC;
    int oy = l / OW, ox = l - oy * OW;

    float g[2] = {0.0f, 0.0f};
#pragma unroll
    for (int e = 0; e < 2; e++) {
        int j = j0 + e;
        if (j < HID) {
            int c  = j / 49;
            int r  = j - c * 49;
            int kh = r / 7, kw = r - kh * 7;
            int iy = kh + 3 * oy;
            int ix = kw + 3 * ox;
            float y = __half2float(pix[(((size_t)b * NCH + c) * HP + iy) * WP + ix]);
            g[e] = gelu_exact(y);
        }
    }
    A2[idx] = __floats2half2_rn(g[0], g[1]);
}

// split-K combine: out = p0 + p1 + bias   (float4)
__global__ void combine_kernel(const float4* __restrict__ p0, const float4* __restrict__ p1,
                               const float4* __restrict__ bias, float4* __restrict__ out)
{
    int idx = blockIdx.x * blockDim.x + threadIdx.x;
    if (idx >= M_TOK * DIM / 4) return;
    float4 a = p0[idx], b = p1[idx];
    float4 bs = bias[idx & (DIM / 4 - 1)];
    out[idx] = make_float4(a.x + b.x + bs.x, a.y + b.y + bs.y,
                           a.z + b.z + bs.z, a.w + b.w + bs.w);
}

// ---------------------------------------------------------------------------
// fp16 mma.sync GEMM. C[m,n] = sum_k A[m,k]*B[n,k] (+ bias[n] if BIAS)
// 128 threads = 4 warps in 2x2 grid of 64x64 warp tiles over BM=BN=128.
// BK=64 halves (SW128), 3-stage cp.async, occ 2.
// blockIdx.z selects K range; C offset by z*part_stride.
// ---------------------------------------------------------------------------
#define STAGES 3
#define NTHREADS 128

__device__ __forceinline__ uint32_t smem_u32(const void* p) {
    return (uint32_t)__cvta_generic_to_shared(p);
}

template<int MINCTA, bool BIAS, typename OutT>
__global__ __launch_bounds__(NTHREADS, MINCTA)
void gemm_fp16_mma(const __half* __restrict__ A, const __half* __restrict__ B,
                   const float* __restrict__ bias, OutT* __restrict__ C,
                   int KTsplit, int KTtotal, int kbytes, int Nstore, int ldc,
                   size_t part_stride)
{
    constexpr int BMt = 128, BNt = 128, WM = 64, WN = 64;
    constexpr int STAGE_BYTES = (BMt + BNt) * 128;   // 32768
    constexpr int A_BYTES     = BMt * 128;           // 16384
    constexpr int NI   = WM / 16;   // 4
    constexpr int NB16 = WN / 16;   // 4
    constexpr int NJ   = WN / 8;    // 8

    extern __shared__ char smem[];
    uint32_t sbase = smem_u32(smem);
    const int tid  = threadIdx.x;
    const int wid  = tid >> 5;
    const int lane = tid & 31;
    const int wm   = wid >> 1;      // 0..1
    const int wn   = wid & 1;       // 0..1
    const int m0   = blockIdx.y * BMt;
    const int n0   = blockIdx.x * BNt;
    const int z    = blockIdx.z;
    const int kt_lo = z ? KTsplit : 0;
    const int kt_hi = z ? KTtotal : KTsplit;
    C += (size_t)z * part_stride;

    const char* Ab = (const char*)A + (size_t)m0 * kbytes;
    const char* Bb = (const char*)B + (size_t)n0 * kbytes;

    float acc[NI][NJ][4];
#pragma unroll
    for (int i = 0; i < NI; i++)
#pragma unroll
        for (int j = 0; j < NJ; j++)
#pragma unroll
            for (int q = 0; q < 4; q++) acc[i][j][q] = 0.0f;

    auto load_stage = [&](int s, int kt2) {
        uint32_t st = sbase + s * STAGE_BYTES;
        size_t koff = (size_t)kt2 * 128;
#pragma unroll
        for (int i = 0; i < BMt * 8 / NTHREADS; i++) {     // 8 iters
            int id  = tid + i * NTHREADS;
            int row = id >> 3;
            int c   = id & 7;
            uint32_t so = (uint32_t)(row * 128 + ((c ^ (row & 7)) << 4));
            const char* ga = Ab + (size_t)row * kbytes + koff + ((size_t)c << 4);
            asm volatile("cp.async.cg.shared.global [%0], [%1], 16;" :: "r"(st + so), "l"(ga) : "memory");
        }
#pragma unroll
        for (int i = 0; i < BNt * 8 / NTHREADS; i++) {     // 8 iters
            int id  = tid + i * NTHREADS;
            int row = id >> 3;
            int c   = id & 7;
            uint32_t so = (uint32_t)(row * 128 + ((c ^ (row & 7)) << 4));
            const char* gb = Bb + (size_t)row * kbytes + koff + ((size_t)c << 4);
            asm volatile("cp.async.cg.shared.global [%0], [%1], 16;" :: "r"(st + A_BYTES + so), "l"(gb) : "memory");
        }
        asm volatile("cp.async.commit_group;" ::: "memory");
    };

    const int lrow = lane & 15;
    const int lch  = lane >> 4;
    uint32_t offA[NI], offB[NB16];
#pragma unroll
    for (int i = 0; i < NI; i++) {
        int r = wm * WM + i * 16 + lrow;
        offA[i] = (uint32_t)(r * 128 + ((lch ^ (r & 7)) << 4));
    }
#pragma unroll
    for (int j = 0; j < NB16; j++) {
        int r = wn * WN + j * 16 + lrow;
        offB[j] = (uint32_t)(A_BYTES + r * 128 + ((lch ^ (r & 7)) << 4));
    }

    // prologue
#pragma unroll
    for (int p = 0; p < STAGES - 1; p++) load_stage(p, kt_lo + p);

    for (int kt = kt_lo; kt < kt_hi; kt++) {
        int s = (kt - kt_lo) % STAGES;
        asm volatile("cp.async.wait_group 1;" ::: "memory");
        __syncthreads();

        int ktn = kt + STAGES - 1;
        if (ktn < kt_hi) load_stage((ktn - kt_lo) % STAGES, ktn);
        else             asm volatile("cp.async.commit_group;" ::: "memory");

        uint32_t sA = sbase + s * STAGE_BYTES;

#pragma unroll
        for (int k16 = 0; k16 < 4; k16++) {
            const uint32_t kx = (uint32_t)(k16 << 5);
            uint32_t a[NI][4], b[NB16][4];
#pragma unroll
            for (int i = 0; i < NI; i++) {
                asm volatile("ldmatrix.sync.aligned.m8n8.x4.shared.b16 {%0,%1,%2,%3}, [%4];"
                             : "=r"(a[i][0]), "=r"(a[i][1]), "=r"(a[i][2]), "=r"(a[i][3])
                             : "r"(sA + (offA[i] ^ kx)));
            }
#pragma unroll
            for (int j = 0; j < NB16; j++) {
                asm volatile("ldmatrix.sync.aligned.m8n8.x4.shared.b16 {%0,%1,%2,%3}, [%4];"
                             : "=r"(b[j][0]), "=r"(b[j][1]), "=r"(b[j][2]), "=r"(b[j][3])
                             : "r"(sA + (offB[j] ^ kx)));
            }
#pragma unroll
            for (int i = 0; i < NI; i++) {
#pragma unroll
                for (int jn = 0; jn < NJ; jn++) {
                    int jj = jn >> 1;
                    uint32_t b0 = (jn & 1) ? b[jj][1] : b[jj][0];
                    uint32_t b1 = (jn & 1) ? b[jj][3] : b[jj][2];
                    asm volatile(
                        "mma.sync.aligned.m16n8k16.row.col.f32.f16.f16.f32 "
                        "{%0,%1,%2,%3}, {%4,%5,%6,%7}, {%8,%9}, {%0,%1,%2,%3};"
                        : "+f"(acc[i][jn][0]), "+f"(acc[i][jn][1]),
                          "+f"(acc[i][jn][2]), "+f"(acc[i][jn][3])
                        : "r"(a[i][0]), "r"(a[i][1]), "r"(a[i][2]), "r"(a[i][3]),
                          "r"(b0), "r"(b1));
                }
            }
        }
    }

    // epilogue
    const int g  = lane >> 2;
    const int tg = lane & 3;
#pragma unroll
    for (int i = 0; i < NI; i++) {
        int r0 = m0 + wm * WM + i * 16 + g;
#pragma unroll
        for (int jn = 0; jn < NJ; jn++) {
            int col = n0 + wn * WN + jn * 8 + tg * 2;
            if (col < Nstore) {
                float bx = BIAS ? bias[col]     : 0.0f;
                float by = BIAS ? bias[col + 1] : 0.0f;
                float c00 = acc[i][jn][0] + bx, c01 = acc[i][jn][1] + by;
                float c10 = acc[i][jn][2] + bx, c11 = acc[i][jn][3] + by;
                if constexpr (sizeof(OutT) == 2) {
                    *reinterpret_cast<__half2*>((__half*)C + (size_t)r0       * ldc + col) = __floats2half2_rn(c00, c01);
                    *reinterpret_cast<__half2*>((__half*)C + (size_t)(r0 + 8) * ldc + col) = __floats2half2_rn(c10, c11);
                } else {
                    *reinterpret_cast<float2*>((float*)C + (size_t)r0       * ldc + col) = make_float2(c00, c01);
                    *reinterpret_cast<float2*>((float*)C + (size_t)(r0 + 8) * ldc + col) = make_float2(c10, c11);
                }
            }
        }
    }
}

// ---------------------------------------------------------------------------
// launch
// ---------------------------------------------------------------------------
extern "C" void kernel_launch(void* const* d_in, const int* in_sizes, int n_in,
                              void* d_out, int out_size)
{
    const float* x  = (const float*)d_in[0];
    const float* W1 = (const float*)d_in[1];
    const float* b1 = (const float*)d_in[2];
    const float* W2 = (const float*)d_in[3];
    const float* b2 = (const float*)d_in[4];
    float* out = (float*)d_out;

    __half *h_ptr, *pix_ptr, *A1, *B1, *A2, *B2;
    float *part_ptr;
    cudaGetSymbolAddress((void**)&h_ptr,   g_h);
    cudaGetSymbolAddress((void**)&pix_ptr, g_pix);
    cudaGetSymbolAddress((void**)&A1, g_A1);
    cudaGetSymbolAddress((void**)&B1, g_B1);
    cudaGetSymbolAddress((void**)&A2, g_A2);
    cudaGetSymbolAddress((void**)&B2, g_B2);
    cudaGetSymbolAddress((void**)&part_ptr, g_part);

    constexpr int GSMEM = STAGES * 256 * 128;   // 98304, occ 2
    cudaFuncSetAttribute((const void*)gemm_fp16_mma<2, true, __half>,
                         cudaFuncAttributeMaxDynamicSharedMemorySize, GSMEM);
    cudaFuncSetAttribute((const void*)gemm_fp16_mma<2, false, float>,
                         cudaFuncAttributeMaxDynamicSharedMemorySize, GSMEM);

    { int n = M_TOK * DIM / 4;   prep_x_kernel <<<(n + 255) / 256, 256>>>((const float4*)x, (__half2*)A1); }
    { int n = N1PAD * DIM / 4;   prep_W1_kernel<<<(n + 255) / 256, 256>>>(W1, (__half2*)B1); }
    { int n = DIM * K2PAD / 4;   prep_W2_kernel<<<(n + 255) / 256, 256>>>(W2, (__half2*)B2); }

    // GEMM1: g_h(fp16) = x @ W1^T + b1   (M=11520, N=1960(pad2048), K=512)
    {
        dim3 grid(N1PAD / 128, M_TOK / 128, 1);   // (16, 90)
        gemm_fp16_mma<2, true, __half><<<grid, NTHREADS, GSMEM>>>(
            A1, B1, b1, h_ptr, DIM / 64, DIM / 64, DIM * 2, HID, HID, 0);
    }
    // fold + normalize + mask (fp16 pix)
    {
        int blocks = (NPIX + 255) / 256;
        fold_div_kernel<<<blocks, 256>>>(h_ptr, pix_ptr);
    }
    // unfold + GELU -> A2 (half2)
    {
        int n = M_TOK * (K2PAD / 2);
        prep_A2_kernel<<<(n + 255) / 256, 256>>>(pix_ptr, (__half2*)A2);
    }
    // GEMM2 split-K partials   (M=11520, N=512, K split 960 + 1024)
    {
        dim3 grid(DIM / 128, M_TOK / 128, 2);     // (4, 90, 2)
        gemm_fp16_mma<2, false, float><<<grid, NTHREADS, GSMEM>>>(
            A2, B2, nullptr, part_ptr, 960 / 64, K2PAD / 64, K2PAD * 2, DIM, DIM,
            (size_t)M_TOK * DIM);
    }
    // combine: out = p0 + p1 + b2
    {
        int n = M_TOK * DIM / 4;
        combine_kernel<<<(n + 255) / 256, 256>>>(
            (const float4*)part_ptr, (const float4*)(part_ptr + (size_t)M_TOK * DIM),
            (const float4*)b2, (float4*)out);
    }
}

// round 12
// speedup vs baseline: 1.0663x; 1.0663x over previous
#include <cuda_runtime.h>
#include <cuda_fp16.h>
#include <math.h>
#include <stdint.h>

#define M_TOK   11520
#define DIM     512
#define HID     1960
#define BPRIME  16
#define NCH     40
#define OH      20
#define OW      36
#define LVEC    720
#define HP      66
#define WP      114
#define NPIX    (BPRIME*HP*WP*NCH)

#define N1PAD   2048
#define K2PAD   1984

// Hidden index is PERMUTED throughout: j' = r*40 + c  (r = kh*7+kw, c = channel)
// pix layout: [b][iy][ix][c] (channel-last)

__device__ __half g_h   [(size_t)M_TOK * HID];
__device__ __half g_pix [(size_t)NPIX];
__device__ __half g_A1  [(size_t)M_TOK * DIM];
__device__ __half g_B1  [(size_t)N1PAD * DIM];
__device__ __half g_A2  [(size_t)M_TOK * K2PAD];
__device__ __half g_B2  [(size_t)DIM   * K2PAD];
__device__ float  g_part[2][(size_t)M_TOK * DIM];
__device__ float  g_b1p [N1PAD];

__device__ __forceinline__ float gelu_exact(float v) {
    return 0.5f * v * (1.0f + erff(v * 0.70710678118654752f));
}

// ---------------------------------------------------------------------------
__global__ void prep_x_kernel(const float4* __restrict__ x, __half2* __restrict__ A1)
{
    int idx = blockIdx.x * blockDim.x + threadIdx.x;
    if (idx >= M_TOK * DIM / 4) return;
    float4 v = x[idx];
    A1[idx * 2 + 0] = __floats2half2_rn(v.x, v.y);
    A1[idx * 2 + 1] = __floats2half2_rn(v.z, v.w);
}

// B1 row n' = perm(n): n = c*49+r -> n' = r*40+c ; rows >= HID stay zero rows
__global__ void prep_W1_kernel(const float* __restrict__ W1, __half* __restrict__ B1)
{
    int idx = blockIdx.x * blockDim.x + threadIdx.x;   // vec4 over N1PAD*DIM
    if (idx >= N1PAD * DIM / 4) return;
    int n = (idx * 4) / DIM;
    int k = (idx * 4) - n * DIM;
    float4 v = make_float4(0.f, 0.f, 0.f, 0.f);
    int nd = n;
    if (n < HID) {
        v = *reinterpret_cast<const float4*>(W1 + (size_t)n * DIM + k);
        int c = n / 49, r = n - c * 49;
        nd = r * NCH + c;
    }
    __half2* dst = reinterpret_cast<__half2*>(B1 + (size_t)nd * DIM + k);
    dst[0] = __floats2half2_rn(v.x, v.y);
    dst[1] = __floats2half2_rn(v.z, v.w);
}

// permuted bias for GEMM1 epilogue
__global__ void prep_b1_kernel(const float* __restrict__ b1, float* __restrict__ b1p)
{
    int n = blockIdx.x * blockDim.x + threadIdx.x;
    if (n >= N1PAD) return;
    if (n < HID) {
        int c = n / 49, r = n - c * 49;
        b1p[r * NCH + c] = b1[n];
    } else {
        b1p[n] = 0.0f;
    }
}

// B2 column j' = perm(j): write coalesced, read W2[n][c*49+r] pairwise
__global__ void prep_W2_kernel(const float* __restrict__ W2, __half2* __restrict__ B2)
{
    int idx = blockIdx.x * blockDim.x + threadIdx.x;   // over DIM * K2PAD/2
    if (idx >= DIM * (K2PAD / 2)) return;
    int n  = idx / (K2PAD / 2);
    int j0 = (idx - n * (K2PAD / 2)) * 2;
    float v0 = 0.f, v1 = 0.f;
    if (j0 < HID) {                                    // j0 even -> c even, same r
        int r = j0 / NCH, c = j0 - r * NCH;
        v0 = W2[(size_t)n * HID + c       * 49 + r];
        v1 = W2[(size_t)n * HID + (c + 1) * 49 + r];
    }
    B2[idx] = __floats2half2_rn(v0, v1);
}

// ---------------------------------------------------------------------------
// fold + normalize + border-mask, channel-last, coalesced
// ---------------------------------------------------------------------------
__global__ void fold_div_kernel(const __half* __restrict__ h, __half* __restrict__ pix)
{
    int idx = blockIdx.x * blockDim.x + threadIdx.x;   // (b, iy, ix, c) c fastest
    if (idx >= NPIX) return;
    int c  = idx % NCH;
    int t  = idx / NCH;
    int ix = t % WP;  t /= WP;
    int iy = t % HP;
    int b  = t / HP;

    float val = 0.0f;
    if (iy >= 3 && iy < 63 && ix >= 3 && ix < 111) {
        int oy_lo = max(0, (iy - 4) / 3);
        int oy_hi = min(OH - 1, iy / 3);
        int ox_lo = max(0, (ix - 4) / 3);
        int ox_hi = min(OW - 1, ix / 3);
        int cnt = (oy_hi - oy_lo + 1) * (ox_hi - ox_lo + 1);
        float acc = 0.0f;
        for (int oy = oy_lo; oy <= oy_hi; oy++) {
            int kh = iy - 3 * oy;
            for (int ox = ox_lo; ox <= ox_hi; ox++) {
                int kw = ix - 3 * ox;
                int token = b * LVEC + oy * OW + ox;
                int r = kh * 7 + kw;
                acc += __half2float(h[(size_t)token * HID + r * NCH + c]);
            }
        }
        val = acc / (float)cnt;
    }
    pix[idx] = __float2half(val);
}

// unfold + GELU -> fp16 A2 (half2, contiguous pix loads)
__global__ void prep_A2_kernel(const __half* __restrict__ pix, __half2* __restrict__ A2)
{
    int idx = blockIdx.x * blockDim.x + threadIdx.x;   // token x K2PAD/2
    if (idx >= M_TOK * (K2PAD / 2)) return;
    int token = idx / (K2PAD / 2);
    int j0    = (idx - token * (K2PAD / 2)) * 2;

    float g0 = 0.0f, g1 = 0.0f;
    if (j0 < HID) {
        int b  = token / LVEC;
        int l  = token - b * LVEC;
        int oy = l / OW, ox = l - oy * OW;
        int r  = j0 / NCH, c = j0 - r * NCH;
        int kh = r / 7, kw = r - kh * 7;
        int iy = kh + 3 * oy;
        int ix = kw + 3 * ox;
        __half2 v = *reinterpret_cast<const __half2*>(
            pix + (((size_t)b * HP + iy) * WP + ix) * NCH + c);
        g0 = gelu_exact(__half2float(__low2half(v)));
        g1 = gelu_exact(__half2float(__high2half(v)));
    }
    A2[idx] = __floats2half2_rn(g0, g1);
}

__global__ void combine_kernel(const float4* __restrict__ p0, const float4* __restrict__ p1,
                               const float4* __restrict__ bias, float4* __restrict__ out)
{
    int idx = blockIdx.x * blockDim.x + threadIdx.x;
    if (idx >= M_TOK * DIM / 4) return;
    float4 a = p0[idx], b = p1[idx];
    float4 bs = bias[idx & (DIM / 4 - 1)];
    out[idx] = make_float4(a.x + b.x + bs.x, a.y + b.y + bs.y,
                           a.z + b.z + bs.z, a.w + b.w + bs.w);
}

// ---------------------------------------------------------------------------
// fp16 mma.sync GEMM (R10 config): 256 thr, BM=BN=128, warp 32x64, occ 2
// ---------------------------------------------------------------------------
#define STAGES 3

__device__ __forceinline__ uint32_t smem_u32(const void* p) {
    return (uint32_t)__cvta_generic_to_shared(p);
}

template<bool BIAS, typename OutT>
__global__ __launch_bounds__(256, 2)
void gemm_fp16_mma(const __half* __restrict__ A, const __half* __restrict__ B,
                   const float* __restrict__ bias, OutT* __restrict__ C,
                   int KTsplit, int KTtotal, int kbytes, int Nstore, int ldc,
                   size_t part_stride)
{
    constexpr int BMt = 128, BNt = 128, WM = 32, WN = 64;
    constexpr int STAGE_BYTES = (BMt + BNt) * 128;
    constexpr int A_BYTES     = BMt * 128;
    constexpr int NWN  = BNt / WN;
    constexpr int NI   = WM / 16;
    constexpr int NB16 = WN / 16;
    constexpr int NJ   = WN / 8;

    extern __shared__ char smem[];
    uint32_t sbase = smem_u32(smem);
    const int tid  = threadIdx.x;
    const int wid  = tid >> 5;
    const int lane = tid & 31;
    const int wm   = wid / NWN;
    const int wn   = wid % NWN;
    const int m0   = blockIdx.y * BMt;
    const int n0   = blockIdx.x * BNt;
    const int z    = blockIdx.z;
    const int kt_lo = z ? KTsplit : 0;
    const int kt_hi = z ? KTtotal : KTsplit;
    C += (size_t)z * part_stride;

    const char* Ab = (const char*)A + (size_t)m0 * kbytes;
    const char* Bb = (const char*)B + (size_t)n0 * kbytes;

    float acc[NI][NJ][4];
#pragma unroll
    for (int i = 0; i < NI; i++)
#pragma unroll
        for (int j = 0; j < NJ; j++)
#pragma unroll
            for (int q = 0; q < 4; q++) acc[i][j][q] = 0.0f;

    auto load_stage = [&](int s, int kt2) {
        uint32_t st = sbase + s * STAGE_BYTES;
        size_t koff = (size_t)kt2 * 128;
#pragma unroll
        for (int i = 0; i < BMt / 32; i++) {
            int id  = tid + i * 256;
            int row = id >> 3;
            int c   = id & 7;
            uint32_t so = (uint32_t)(row * 128 + ((c ^ (row & 7)) << 4));
            const char* ga = Ab + (size_t)row * kbytes + koff + ((size_t)c << 4);
            asm volatile("cp.async.cg.shared.global [%0], [%1], 16;" :: "r"(st + so), "l"(ga) : "memory");
        }
#pragma unroll
        for (int i = 0; i < BNt / 32; i++) {
            int id  = tid + i * 256;
            int row = id >> 3;
            int c   = id & 7;
            uint32_t so = (uint32_t)(row * 128 + ((c ^ (row & 7)) << 4));
            const char* gb = Bb + (size_t)row * kbytes + koff + ((size_t)c << 4);
            asm volatile("cp.async.cg.shared.global [%0], [%1], 16;" :: "r"(st + A_BYTES + so), "l"(gb) : "memory");
        }
        asm volatile("cp.async.commit_group;" ::: "memory");
    };

    const int lrow = lane & 15;
    const int lch  = lane >> 4;
    uint32_t offA[NI], offB[NB16];
#pragma unroll
    for (int i = 0; i < NI; i++) {
        int r = wm * WM + i * 16 + lrow;
        offA[i] = (uint32_t)(r * 128 + ((lch ^ (r & 7)) << 4));
    }
#pragma unroll
    for (int j = 0; j < NB16; j++) {
        int r = wn * WN + j * 16 + lrow;
        offB[j] = (uint32_t)(A_BYTES + r * 128 + ((lch ^ (r & 7)) << 4));
    }

#pragma unroll
    for (int p = 0; p < STAGES - 1; p++) load_stage(p, kt_lo + p);

    for (int kt = kt_lo; kt < kt_hi; kt++) {
        int s = (kt - kt_lo) % STAGES;
        asm volatile("cp.async.wait_group 1;" ::: "memory");
        __syncthreads();

        int ktn = kt + STAGES - 1;
        if (ktn < kt_hi) load_stage((ktn - kt_lo) % STAGES, ktn);
        else             asm volatile("cp.async.commit_group;" ::: "memory");

        uint32_t sA = sbase + s * STAGE_BYTES;

#pragma unroll
        for (int k16 = 0; k16 < 4; k16++) {
            const uint32_t kx = (uint32_t)(k16 << 5);
            uint32_t a[NI][4], b[NB16][4];
#pragma unroll
            for (int i = 0; i < NI; i++) {
                asm volatile("ldmatrix.sync.aligned.m8n8.x4.shared.b16 {%0,%1,%2,%3}, [%4];"
                             : "=r"(a[i][0]), "=r"(a[i][1]), "=r"(a[i][2]), "=r"(a[i][3])
                             : "r"(sA + (offA[i] ^ kx)));
            }
#pragma unroll
            for (int j = 0; j < NB16; j++) {
                asm volatile("ldmatrix.sync.aligned.m8n8.x4.shared.b16 {%0,%1,%2,%3}, [%4];"
                             : "=r"(b[j][0]), "=r"(b[j][1]), "=r"(b[j][2]), "=r"(b[j][3])
                             : "r"(sA + (offB[j] ^ kx)));
            }
#pragma unroll
            for (int i = 0; i < NI; i++) {
#pragma unroll
                for (int jn = 0; jn < NJ; jn++) {
                    int jj = jn >> 1;
                    uint32_t b0 = (jn & 1) ? b[jj][1] : b[jj][0];
                    uint32_t b1 = (jn & 1) ? b[jj][3] : b[jj][2];
                    asm volatile(
                        "mma.sync.aligned.m16n8k16.row.col.f32.f16.f16.f32 "
                        "{%0,%1,%2,%3}, {%4,%5,%6,%7}, {%8,%9}, {%0,%1,%2,%3};"
                        : "+f"(acc[i][jn][0]), "+f"(acc[i][jn][1]),
                          "+f"(acc[i][jn][2]), "+f"(acc[i][jn][3])
                        : "r"(a[i][0]), "r"(a[i][1]), "r"(a[i][2]), "r"(a[i][3]),
                          "r"(b0), "r"(b1));
                }
            }
        }
    }

    const int g  = lane >> 2;
    const int tg = lane & 3;
#pragma unroll
    for (int i = 0; i < NI; i++) {
        int r0 = m0 + wm * WM + i * 16 + g;
#pragma unroll
        for (int jn = 0; jn < NJ; jn++) {
            int col = n0 + wn * WN + jn * 8 + tg * 2;
            if (col < Nstore) {
                float bx = BIAS ? bias[col]     : 0.0f;
                float by = BIAS ? bias[col + 1] : 0.0f;
                float c00 = acc[i][jn][0] + bx, c01 = acc[i][jn][1] + by;
                float c10 = acc[i][jn][2] + bx, c11 = acc[i][jn][3] + by;
                if constexpr (sizeof(OutT) == 2) {
                    *reinterpret_cast<__half2*>((__half*)C + (size_t)r0       * ldc + col) = __floats2half2_rn(c00, c01);
                    *reinterpret_cast<__half2*>((__half*)C + (size_t)(r0 + 8) * ldc + col) = __floats2half2_rn(c10, c11);
                } else {
                    *reinterpret_cast<float2*>((float*)C + (size_t)r0       * ldc + col) = make_float2(c00, c01);
                    *reinterpret_cast<float2*>((float*)C + (size_t)(r0 + 8) * ldc + col) = make_float2(c10, c11);
                }
            }
        }
    }
}

// ---------------------------------------------------------------------------
extern "C" void kernel_launch(void* const* d_in, const int* in_sizes, int n_in,
                              void* d_out, int out_size)
{
    const float* x  = (const float*)d_in[0];
    const float* W1 = (const float*)d_in[1];
    const float* b1 = (const float*)d_in[2];
    const float* W2 = (const float*)d_in[3];
    const float* b2 = (const float*)d_in[4];
    float* out = (float*)d_out;

    __half *h_ptr, *pix_ptr, *A1, *B1, *A2, *B2;
    float *part_ptr, *b1p_ptr;
    cudaGetSymbolAddress((void**)&h_ptr,   g_h);
    cudaGetSymbolAddress((void**)&pix_ptr, g_pix);
    cudaGetSymbolAddress((void**)&A1, g_A1);
    cudaGetSymbolAddress((void**)&B1, g_B1);
    cudaGetSymbolAddress((void**)&A2, g_A2);
    cudaGetSymbolAddress((void**)&B2, g_B2);
    cudaGetSymbolAddress((void**)&part_ptr, g_part);
    cudaGetSymbolAddress((void**)&b1p_ptr,  g_b1p);

    constexpr int GSMEM = STAGES * 256 * 128;   // 98304, occ 2
    cudaFuncSetAttribute((const void*)gemm_fp16_mma<true, __half>,
                         cudaFuncAttributeMaxDynamicSharedMemorySize, GSMEM);
    cudaFuncSetAttribute((const void*)gemm_fp16_mma<false, float>,
                         cudaFuncAttributeMaxDynamicSharedMemorySize, GSMEM);

    { int n = M_TOK * DIM / 4;     prep_x_kernel <<<(n + 255) / 256, 256>>>((const float4*)x, (__half2*)A1); }
    { int n = N1PAD * DIM / 4;     prep_W1_kernel<<<(n + 255) / 256, 256>>>(W1, B1); }
    prep_b1_kernel<<<(N1PAD + 255) / 256, 256>>>(b1, b1p_ptr);
    { int n = DIM * (K2PAD / 2);   prep_W2_kernel<<<(n + 255) / 256, 256>>>(W2, (__half2*)B2); }

    // GEMM1 (permuted N): g_h = x @ B1^T + b1p
    {
        dim3 grid(N1PAD / 128, M_TOK / 128, 1);
        gemm_fp16_mma<true, __half><<<grid, 256, GSMEM>>>(
            A1, B1, b1p_ptr, h_ptr, DIM / 64, DIM / 64, DIM * 2, HID, HID, 0);
    }
    // fold + normalize (coalesced channel-last)
    {
        int blocks = (NPIX + 255) / 256;
        fold_div_kernel<<<blocks, 256>>>(h_ptr, pix_ptr);
    }
    // unfold + GELU -> A2 (permuted K)
    {
        int n = M_TOK * (K2PAD / 2);
        prep_A2_kernel<<<(n + 255) / 256, 256>>>(pix_ptr, (__half2*)A2);
    }
    // GEMM2 split-K partials
    {
        dim3 grid(DIM / 128, M_TOK / 128, 2);
        gemm_fp16_mma<false, float><<<grid, 256, GSMEM>>>(
            A2, B2, nullptr, part_ptr, 960 / 64, K2PAD / 64, K2PAD * 2, DIM, DIM,
            (size_t)M_TOK * DIM);
    }
    // combine
    {
        int n = M_TOK * DIM / 4;
        combine_kernel<<<(n + 255) / 256, 256>>>(
            (const float4*)part_ptr, (const float4*)(part_ptr + (size_t)M_TOK * DIM),
            (const float4*)b2, (float4*)out);
    }
}

// round 13
// speedup vs baseline: 1.1649x; 1.0924x over previous
#include <cuda_runtime.h>
#include <cuda_fp16.h>
#include <math.h>
#include <stdint.h>

#define M_TOK   11520
#define DIM     512
#define HID     1960
#define BPRIME  16
#define NCH     40
#define OH      20
#define OW      36
#define LVEC    720
#define HP      66
#define WP      114
#define NPIX    (BPRIME*HP*WP*NCH)

#define N1PAD   2048
#define K2PAD   1984

// Hidden index is PERMUTED throughout: j' = r*40 + c  (r = kh*7+kw, c = channel)
// pix layout: [b][iy][ix][c] (channel-last)

__device__ __half g_h   [(size_t)M_TOK * HID];
__device__ __half g_pix [(size_t)NPIX];
__device__ __half g_A1  [(size_t)M_TOK * DIM];
__device__ __half g_B1  [(size_t)N1PAD * DIM];
__device__ __half g_A2  [(size_t)M_TOK * K2PAD];
__device__ __half g_B2  [(size_t)DIM   * K2PAD];
__device__ float  g_part[2][(size_t)M_TOK * DIM];
__device__ float  g_b1p [N1PAD];

__device__ __forceinline__ float gelu_exact(float v) {
    return 0.5f * v * (1.0f + erff(v * 0.70710678118654752f));
}

// ---------------------------------------------------------------------------
// merged operand prep: one launch, blockIdx-partitioned
//   [0, NB_X)            : x -> A1 (fp16)
//   [NB_X, +NB_W1)       : W1 -> B1 (row-permuted fp16)
//   [.., +NB_B1)         : b1 -> b1p (permuted fp32)
//   [.., +NB_W2)         : W2 -> B2 (col-permuted fp16)
// ---------------------------------------------------------------------------
#define NB_X   ((M_TOK * DIM / 4 + 255) / 256)              // 2880... (11520*512/4=1474560 /256 = 5760)
#define NB_W1  ((N1PAD * DIM / 4 + 255) / 256)              // 1024
#define NB_B1  ((N1PAD + 255) / 256)                        // 8
#define NB_W2  ((DIM * (K2PAD / 2) + 255) / 256)            // 1984
#define NB_ALL (NB_X + NB_W1 + NB_B1 + NB_W2)

__global__ __launch_bounds__(256)
void prep_all_kernel(const float4* __restrict__ x,  __half2* __restrict__ A1,
                     const float*  __restrict__ W1, __half*  __restrict__ B1,
                     const float*  __restrict__ b1, float*   __restrict__ b1p,
                     const float*  __restrict__ W2, __half2* __restrict__ B2)
{
    int blk = blockIdx.x;
    if (blk < NB_X) {
        int idx = blk * 256 + threadIdx.x;
        if (idx >= M_TOK * DIM / 4) return;
        float4 v = x[idx];
        A1[idx * 2 + 0] = __floats2half2_rn(v.x, v.y);
        A1[idx * 2 + 1] = __floats2half2_rn(v.z, v.w);
        return;
    }
    blk -= NB_X;
    if (blk < NB_W1) {
        int idx = blk * 256 + threadIdx.x;
        if (idx >= N1PAD * DIM / 4) return;
        int n = (idx * 4) / DIM;
        int k = (idx * 4) - n * DIM;
        float4 v = make_float4(0.f, 0.f, 0.f, 0.f);
        int nd = n;
        if (n < HID) {
            v = *reinterpret_cast<const float4*>(W1 + (size_t)n * DIM + k);
            int c = n / 49, r = n - c * 49;
            nd = r * NCH + c;
        }
        __half2* dst = reinterpret_cast<__half2*>(B1 + (size_t)nd * DIM + k);
        dst[0] = __floats2half2_rn(v.x, v.y);
        dst[1] = __floats2half2_rn(v.z, v.w);
        return;
    }
    blk -= NB_W1;
    if (blk < NB_B1) {
        int n = blk * 256 + threadIdx.x;
        if (n >= N1PAD) return;
        if (n < HID) {
            int c = n / 49, r = n - c * 49;
            b1p[r * NCH + c] = b1[n];
        } else {
            b1p[n] = 0.0f;
        }
        return;
    }
    blk -= NB_B1;
    {
        int idx = blk * 256 + threadIdx.x;
        if (idx >= DIM * (K2PAD / 2)) return;
        int n  = idx / (K2PAD / 2);
        int j0 = (idx - n * (K2PAD / 2)) * 2;
        float v0 = 0.f, v1 = 0.f;
        if (j0 < HID) {
            int r = j0 / NCH, c = j0 - r * NCH;
            v0 = W2[(size_t)n * HID + c       * 49 + r];
            v1 = W2[(size_t)n * HID + (c + 1) * 49 + r];
        }
        B2[idx] = __floats2half2_rn(v0, v1);
    }
}

// ---------------------------------------------------------------------------
// fold + normalize + border-mask, channel-last, half2 (2 channels / thread)
// ---------------------------------------------------------------------------
__global__ __launch_bounds__(256)
void fold_div_kernel(const __half* __restrict__ h, __half2* __restrict__ pix)
{
    int idx = blockIdx.x * blockDim.x + threadIdx.x;   // (b, iy, ix, cpair)
    if (idx >= NPIX / 2) return;
    int cp = idx % (NCH / 2);
    int t  = idx / (NCH / 2);
    int ix = t % WP;  t /= WP;
    int iy = t % HP;
    int b  = t / HP;
    int c0 = cp * 2;

    float v0 = 0.0f, v1 = 0.0f;
    if (iy >= 3 && iy < 63 && ix >= 3 && ix < 111) {
        int oy_lo = max(0, (iy - 4) / 3);
        int oy_hi = min(OH - 1, iy / 3);
        int ox_lo = max(0, (ix - 4) / 3);
        int ox_hi = min(OW - 1, ix / 3);
        float inv = 1.0f / (float)((oy_hi - oy_lo + 1) * (ox_hi - ox_lo + 1));
        float a0 = 0.0f, a1 = 0.0f;
        for (int oy = oy_lo; oy <= oy_hi; oy++) {
            int kh = iy - 3 * oy;
            for (int ox = ox_lo; ox <= ox_hi; ox++) {
                int kw = ix - 3 * ox;
                int token = b * LVEC + oy * OW + ox;
                int r = kh * 7 + kw;
                __half2 hv = *reinterpret_cast<const __half2*>(
                    h + (size_t)token * HID + r * NCH + c0);
                a0 += __half2float(__low2half(hv));
                a1 += __half2float(__high2half(hv));
            }
        }
        v0 = a0 * inv;
        v1 = a1 * inv;
    }
    pix[idx] = __floats2half2_rn(v0, v1);
}

// unfold + GELU -> fp16 A2 (half2, contiguous pix loads)
__global__ __launch_bounds__(256)
void prep_A2_kernel(const __half* __restrict__ pix, __half2* __restrict__ A2)
{
    int idx = blockIdx.x * blockDim.x + threadIdx.x;   // token x K2PAD/2
    if (idx >= M_TOK * (K2PAD / 2)) return;
    int token = idx / (K2PAD / 2);
    int j0    = (idx - token * (K2PAD / 2)) * 2;

    float g0 = 0.0f, g1 = 0.0f;
    if (j0 < HID) {
        int b  = token / LVEC;
        int l  = token - b * LVEC;
        int oy = l / OW, ox = l - oy * OW;
        int r  = j0 / NCH, c = j0 - r * NCH;
        int kh = r / 7, kw = r - kh * 7;
        int iy = kh + 3 * oy;
        int ix = kw + 3 * ox;
        __half2 v = *reinterpret_cast<const __half2*>(
            pix + (((size_t)b * HP + iy) * WP + ix) * NCH + c);
        g0 = gelu_exact(__half2float(__low2half(v)));
        g1 = gelu_exact(__half2float(__high2half(v)));
    }
    A2[idx] = __floats2half2_rn(g0, g1);
}

__global__ __launch_bounds__(256)
void combine_kernel(const float4* __restrict__ p0, const float4* __restrict__ p1,
                    const float4* __restrict__ bias, float4* __restrict__ out)
{
    int idx = blockIdx.x * blockDim.x + threadIdx.x;
    if (idx >= M_TOK * DIM / 4) return;
    float4 a = p0[idx], b = p1[idx];
    float4 bs = bias[idx & (DIM / 4 - 1)];
    out[idx] = make_float4(a.x + b.x + bs.x, a.y + b.y + bs.y,
                           a.z + b.z + bs.z, a.w + b.w + bs.w);
}

// ---------------------------------------------------------------------------
// fp16 mma.sync GEMM: 256 thr, BM=BN=128, warp 32x64, occ 2, 3-stage cp.async,
// optional split-K via blockIdx.z.
// ---------------------------------------------------------------------------
#define STAGES 3

__device__ __forceinline__ uint32_t smem_u32(const void* p) {
    return (uint32_t)__cvta_generic_to_shared(p);
}

template<bool BIAS, typename OutT>
__global__ __launch_bounds__(256, 2)
void gemm_fp16_mma(const __half* __restrict__ A, const __half* __restrict__ B,
                   const float* __restrict__ bias, OutT* __restrict__ C,
                   int KTsplit, int KTtotal, int kbytes, int Nstore, int ldc,
                   size_t part_stride)
{
    constexpr int BMt = 128, BNt = 128, WM = 32, WN = 64;
    constexpr int STAGE_BYTES = (BMt + BNt) * 128;
    constexpr int A_BYTES     = BMt * 128;
    constexpr int NWN  = BNt / WN;
    constexpr int NI   = WM / 16;
    constexpr int NB16 = WN / 16;
    constexpr int NJ   = WN / 8;

    extern __shared__ char smem[];
    uint32_t sbase = smem_u32(smem);
    const int tid  = threadIdx.x;
    const int wid  = tid >> 5;
    const int lane = tid & 31;
    const int wm   = wid / NWN;
    const int wn   = wid % NWN;
    const int m0   = blockIdx.y * BMt;
    const int n0   = blockIdx.x * BNt;
    const int z    = blockIdx.z;
    const int kt_lo = z ? KTsplit : 0;
    const int kt_hi = z ? KTtotal : KTsplit;
    C += (size_t)z * part_stride;

    const char* Ab = (const char*)A + (size_t)m0 * kbytes;
    const char* Bb = (const char*)B + (size_t)n0 * kbytes;

    float acc[NI][NJ][4];
#pragma unroll
    for (int i = 0; i < NI; i++)
#pragma unroll
        for (int j = 0; j < NJ; j++)
#pragma unroll
            for (int q = 0; q < 4; q++) acc[i][j][q] = 0.0f;

    auto load_stage = [&](int s, int kt2) {
        uint32_t st = sbase + s * STAGE_BYTES;
        size_t koff = (size_t)kt2 * 128;
#pragma unroll
        for (int i = 0; i < BMt / 32; i++) {
            int id  = tid + i * 256;
            int row = id >> 3;
            int c   = id & 7;
            uint32_t so = (uint32_t)(row * 128 + ((c ^ (row & 7)) << 4));
            const char* ga = Ab + (size_t)row * kbytes + koff + ((size_t)c << 4);
            asm volatile("cp.async.cg.shared.global [%0], [%1], 16;" :: "r"(st + so), "l"(ga) : "memory");
        }
#pragma unroll
        for (int i = 0; i < BNt / 32; i++) {
            int id  = tid + i * 256;
            int row = id >> 3;
            int c   = id & 7;
            uint32_t so = (uint32_t)(row * 128 + ((c ^ (row & 7)) << 4));
            const char* gb = Bb + (size_t)row * kbytes + koff + ((size_t)c << 4);
            asm volatile("cp.async.cg.shared.global [%0], [%1], 16;" :: "r"(st + A_BYTES + so), "l"(gb) : "memory");
        }
        asm volatile("cp.async.commit_group;" ::: "memory");
    };

    const int lrow = lane & 15;
    const int lch  = lane >> 4;
    uint32_t offA[NI], offB[NB16];
#pragma unroll
    for (int i = 0; i < NI; i++) {
        int r = wm * WM + i * 16 + lrow;
        offA[i] = (uint32_t)(r * 128 + ((lch ^ (r & 7)) << 4));
    }
#pragma unroll
    for (int j = 0; j < NB16; j++) {
        int r = wn * WN + j * 16 + lrow;
        offB[j] = (uint32_t)(A_BYTES + r * 128 + ((lch ^ (r & 7)) << 4));
    }

#pragma unroll
    for (int p = 0; p < STAGES - 1; p++) load_stage(p, kt_lo + p);

    for (int kt = kt_lo; kt < kt_hi; kt++) {
        int s = (kt - kt_lo) % STAGES;
        asm volatile("cp.async.wait_group 1;" ::: "memory");
        __syncthreads();

        int ktn = kt + STAGES - 1;
        if (ktn < kt_hi) load_stage((ktn - kt_lo) % STAGES, ktn);
        else             asm volatile("cp.async.commit_group;" ::: "memory");

        uint32_t sA = sbase + s * STAGE_BYTES;

#pragma unroll
        for (int k16 = 0; k16 < 4; k16++) {
            const uint32_t kx = (uint32_t)(k16 << 5);
            uint32_t a[NI][4], b[NB16][4];
#pragma unroll
            for (int i = 0; i < NI; i++) {
                asm volatile("ldmatrix.sync.aligned.m8n8.x4.shared.b16 {%0,%1,%2,%3}, [%4];"
                             : "=r"(a[i][0]), "=r"(a[i][1]), "=r"(a[i][2]), "=r"(a[i][3])
                             : "r"(sA + (offA[i] ^ kx)));
            }
#pragma unroll
            for (int j = 0; j < NB16; j++) {
                asm volatile("ldmatrix.sync.aligned.m8n8.x4.shared.b16 {%0,%1,%2,%3}, [%4];"
                             : "=r"(b[j][0]), "=r"(b[j][1]), "=r"(b[j][2]), "=r"(b[j][3])
                             : "r"(sA + (offB[j] ^ kx)));
            }
#pragma unroll
            for (int i = 0; i < NI; i++) {
#pragma unroll
                for (int jn = 0; jn < NJ; jn++) {
                    int jj = jn >> 1;
                    uint32_t b0 = (jn & 1) ? b[jj][1] : b[jj][0];
                    uint32_t b1 = (jn & 1) ? b[jj][3] : b[jj][2];
                    asm volatile(
                        "mma.sync.aligned.m16n8k16.row.col.f32.f16.f16.f32 "
                        "{%0,%1,%2,%3}, {%4,%5,%6,%7}, {%8,%9}, {%0,%1,%2,%3};"
                        : "+f"(acc[i][jn][0]), "+f"(acc[i][jn][1]),
                          "+f"(acc[i][jn][2]), "+f"(acc[i][jn][3])
                        : "r"(a[i][0]), "r"(a[i][1]), "r"(a[i][2]), "r"(a[i][3]),
                          "r"(b0), "r"(b1));
                }
            }
        }
    }

    const int g  = lane >> 2;
    const int tg = lane & 3;
#pragma unroll
    for (int i = 0; i < NI; i++) {
        int r0 = m0 + wm * WM + i * 16 + g;
#pragma unroll
        for (int jn = 0; jn < NJ; jn++) {
            int col = n0 + wn * WN + jn * 8 + tg * 2;
            if (col < Nstore) {
                float bx = BIAS ? bias[col]     : 0.0f;
                float by = BIAS ? bias[col + 1] : 0.0f;
                float c00 = acc[i][jn][0] + bx, c01 = acc[i][jn][1] + by;
                float c10 = acc[i][jn][2] + bx, c11 = acc[i][jn][3] + by;
                if constexpr (sizeof(OutT) == 2) {
                    *reinterpret_cast<__half2*>((__half*)C + (size_t)r0       * ldc + col) = __floats2half2_rn(c00, c01);
                    *reinterpret_cast<__half2*>((__half*)C + (size_t)(r0 + 8) * ldc + col) = __floats2half2_rn(c10, c11);
                } else {
                    *reinterpret_cast<float2*>((float*)C + (size_t)r0       * ldc + col) = make_float2(c00, c01);
                    *reinterpret_cast<float2*>((float*)C + (size_t)(r0 + 8) * ldc + col) = make_float2(c10, c11);
                }
            }
        }
    }
}

// ---------------------------------------------------------------------------
extern "C" void kernel_launch(void* const* d_in, const int* in_sizes, int n_in,
                              void* d_out, int out_size)
{
    const float* x  = (const float*)d_in[0];
    const float* W1 = (const float*)d_in[1];
    const float* b1 = (const float*)d_in[2];
    const float* W2 = (const float*)d_in[3];
    const float* b2 = (const float*)d_in[4];
    float* out = (float*)d_out;

    __half *h_ptr, *pix_ptr, *A1, *B1, *A2, *B2;
    float *part_ptr, *b1p_ptr;
    cudaGetSymbolAddress((void**)&h_ptr,   g_h);
    cudaGetSymbolAddress((void**)&pix_ptr, g_pix);
    cudaGetSymbolAddress((void**)&A1, g_A1);
    cudaGetSymbolAddress((void**)&B1, g_B1);
    cudaGetSymbolAddress((void**)&A2, g_A2);
    cudaGetSymbolAddress((void**)&B2, g_B2);
    cudaGetSymbolAddress((void**)&part_ptr, g_part);
    cudaGetSymbolAddress((void**)&b1p_ptr,  g_b1p);

    constexpr int GSMEM = STAGES * 256 * 128;   // 98304, occ 2
    cudaFuncSetAttribute((const void*)gemm_fp16_mma<true, __half>,
                         cudaFuncAttributeMaxDynamicSharedMemorySize, GSMEM);
    cudaFuncSetAttribute((const void*)gemm_fp16_mma<false, float>,
                         cudaFuncAttributeMaxDynamicSharedMemorySize, GSMEM);

    // merged operand prep (1 launch)
    prep_all_kernel<<<NB_ALL, 256>>>((const float4*)x, (__half2*)A1,
                                     W1, B1, b1, b1p_ptr, W2, (__half2*)B2);

    // GEMM1 (permuted N): g_h = x @ B1^T + b1p
    {
        dim3 grid(N1PAD / 128, M_TOK / 128, 1);
        gemm_fp16_mma<true, __half><<<grid, 256, GSMEM>>>(
            A1, B1, b1p_ptr, h_ptr, DIM / 64, DIM / 64, DIM * 2, HID, HID, 0);
    }
    // fold + normalize (channel-last, half2)
    {
        int n = NPIX / 2;
        fold_div_kernel<<<(n + 255) / 256, 256>>>(h_ptr, (__half2*)pix_ptr);
    }
    // unfold + GELU -> A2 (permuted K)
    {
        int n = M_TOK * (K2PAD / 2);
        prep_A2_kernel<<<(n + 255) / 256, 256>>>(pix_ptr, (__half2*)A2);
    }
    // GEMM2 split-K partials
    {
        dim3 grid(DIM / 128, M_TOK / 128, 2);
        gemm_fp16_mma<false, float><<<grid, 256, GSMEM>>>(
            A2, B2, nullptr, part_ptr, 960 / 64, K2PAD / 64, K2PAD * 2, DIM, DIM,
            (size_t)M_TOK * DIM);
    }
    // combine
    {
        int n = M_TOK * DIM / 4;
        combine_kernel<<<(n + 255) / 256, 256>>>(
            (const float4*)part_ptr, (const float4*)(part_ptr + (size_t)M_TOK * DIM),
            (const float4*)b2, (float4*)out);
    }
}

// round 14
// speedup vs baseline: 1.3569x; 1.1649x over previous
#include <cuda_runtime.h>
#include <cuda_fp16.h>
#include <math.h>
#include <stdint.h>

#define M_TOK   11520
#define DIM     512
#define HID     1960
#define BPRIME  16
#define NCH     40
#define OH      20
#define OW      36
#define LVEC    720
#define HP      66
#define WP      114
#define NPIX    (BPRIME*HP*WP*NCH)

#define N1PAD   2048
#define K2PAD   1984

// Hidden index is PERMUTED throughout: j' = r*40 + c  (r = kh*7+kw, c = channel)
// pix layout: [b][iy][ix][c] (channel-last), stores gelu(normalized fold)

__device__ __half g_h   [(size_t)M_TOK * HID];
__device__ __half g_pix [(size_t)NPIX];
__device__ __half g_A1  [(size_t)M_TOK * DIM];
__device__ __half g_B1  [(size_t)N1PAD * DIM];
__device__ __half g_A2  [(size_t)M_TOK * K2PAD];
__device__ __half g_B2  [(size_t)DIM   * K2PAD];
__device__ float  g_part[2][(size_t)M_TOK * DIM];
__device__ float  g_b1p [N1PAD];

__device__ __forceinline__ float gelu_exact(float v) {
    return 0.5f * v * (1.0f + erff(v * 0.70710678118654752f));
}

// ---------------------------------------------------------------------------
// merged operand prep: one launch, blockIdx-partitioned
// ---------------------------------------------------------------------------
#define NB_X   ((M_TOK * DIM / 4 + 255) / 256)
#define NB_W1  ((N1PAD * DIM / 4 + 255) / 256)
#define NB_B1  ((N1PAD + 255) / 256)
#define NB_W2  ((DIM * (K2PAD / 2) + 255) / 256)
#define NB_ALL (NB_X + NB_W1 + NB_B1 + NB_W2)

__global__ __launch_bounds__(256)
void prep_all_kernel(const float4* __restrict__ x,  __half2* __restrict__ A1,
                     const float*  __restrict__ W1, __half*  __restrict__ B1,
                     const float*  __restrict__ b1, float*   __restrict__ b1p,
                     const float*  __restrict__ W2, __half2* __restrict__ B2)
{
    int blk = blockIdx.x;
    if (blk < NB_X) {
        int idx = blk * 256 + threadIdx.x;
        if (idx >= M_TOK * DIM / 4) return;
        float4 v = x[idx];
        A1[idx * 2 + 0] = __floats2half2_rn(v.x, v.y);
        A1[idx * 2 + 1] = __floats2half2_rn(v.z, v.w);
        return;
    }
    blk -= NB_X;
    if (blk < NB_W1) {
        int idx = blk * 256 + threadIdx.x;
        if (idx >= N1PAD * DIM / 4) return;
        int n = (idx * 4) / DIM;
        int k = (idx * 4) - n * DIM;
        float4 v = make_float4(0.f, 0.f, 0.f, 0.f);
        int nd = n;
        if (n < HID) {
            v = *reinterpret_cast<const float4*>(W1 + (size_t)n * DIM + k);
            int c = n / 49, r = n - c * 49;
            nd = r * NCH + c;
        }
        __half2* dst = reinterpret_cast<__half2*>(B1 + (size_t)nd * DIM + k);
        dst[0] = __floats2half2_rn(v.x, v.y);
        dst[1] = __floats2half2_rn(v.z, v.w);
        return;
    }
    blk -= NB_W1;
    if (blk < NB_B1) {
        int n = blk * 256 + threadIdx.x;
        if (n >= N1PAD) return;
        if (n < HID) {
            int c = n / 49, r = n - c * 49;
            b1p[r * NCH + c] = b1[n];
        } else {
            b1p[n] = 0.0f;
        }
        return;
    }
    blk -= NB_B1;
    {
        int idx = blk * 256 + threadIdx.x;
        if (idx >= DIM * (K2PAD / 2)) return;
        int n  = idx / (K2PAD / 2);
        int j0 = (idx - n * (K2PAD / 2)) * 2;
        float v0 = 0.f, v1 = 0.f;
        if (j0 < HID) {
            int r = j0 / NCH, c = j0 - r * NCH;
            v0 = W2[(size_t)n * HID + c       * 49 + r];
            v1 = W2[(size_t)n * HID + (c + 1) * 49 + r];
        }
        B2[idx] = __floats2half2_rn(v0, v1);
    }
}

// ---------------------------------------------------------------------------
// fold + normalize + border-mask + GELU, channel-last, half2
// (gelu commutes through the unfold gather: unfold(gelu(pix)) == gelu(unfold(pix)))
// ---------------------------------------------------------------------------
__global__ __launch_bounds__(256)
void fold_div_kernel(const __half* __restrict__ h, __half2* __restrict__ pix)
{
    int idx = blockIdx.x * blockDim.x + threadIdx.x;   // (b, iy, ix, cpair)
    if (idx >= NPIX / 2) return;
    int cp = idx % (NCH / 2);
    int t  = idx / (NCH / 2);
    int ix = t % WP;  t /= WP;
    int iy = t % HP;
    int b  = t / HP;
    int c0 = cp * 2;

    float v0 = 0.0f, v1 = 0.0f;
    if (iy >= 3 && iy < 63 && ix >= 3 && ix < 111) {
        int oy_lo = max(0, (iy - 4) / 3);
        int oy_hi = min(OH - 1, iy / 3);
        int ox_lo = max(0, (ix - 4) / 3);
        int ox_hi = min(OW - 1, ix / 3);
        float inv = 1.0f / (float)((oy_hi - oy_lo + 1) * (ox_hi - ox_lo + 1));
        float a0 = 0.0f, a1 = 0.0f;
        for (int oy = oy_lo; oy <= oy_hi; oy++) {
            int kh = iy - 3 * oy;
            for (int ox = ox_lo; ox <= ox_hi; ox++) {
                int kw = ix - 3 * ox;
                int token = b * LVEC + oy * OW + ox;
                int r = kh * 7 + kw;
                __half2 hv = *reinterpret_cast<const __half2*>(
                    h + (size_t)token * HID + r * NCH + c0);
                a0 += __half2float(__low2half(hv));
                a1 += __half2float(__high2half(hv));
            }
        }
        v0 = gelu_exact(a0 * inv);
        v1 = gelu_exact(a1 * inv);
    }
    pix[idx] = __floats2half2_rn(v0, v1);
}

// ---------------------------------------------------------------------------
// unfold -> A2 : pure int4 gather/copy (NCH = 40 = 5 x 8 halves)
// one thread = one 16B chunk; 248 chunks per token (245 data + 3 zero pad)
// ---------------------------------------------------------------------------
#define CPT 248   // chunks per token = K2PAD/8

__global__ __launch_bounds__(256)
void prep_A2_kernel(const __half* __restrict__ pix, int4* __restrict__ A2)
{
    int idx = blockIdx.x * blockDim.x + threadIdx.x;
    if (idx >= M_TOK * CPT) return;
    int token = idx / CPT;
    int q     = idx - token * CPT;

    int4 v = make_int4(0, 0, 0, 0);
    if (q < 245) {
        int r = q / 5;
        int c = (q - r * 5) * 8;
        int b  = token / LVEC;
        int l  = token - b * LVEC;
        int oy = l / OW, ox = l - oy * OW;
        int kh = r / 7, kw = r - kh * 7;
        int iy = kh + 3 * oy;
        int ix = kw + 3 * ox;
        v = *reinterpret_cast<const int4*>(
            pix + (((size_t)b * HP + iy) * WP + ix) * NCH + c);
    }
    A2[idx] = v;   // A2 int4 index: token*248 + q  == (token*K2PAD + q*8)/8
}

__global__ __launch_bounds__(256)
void combine_kernel(const float4* __restrict__ p0, const float4* __restrict__ p1,
                    const float4* __restrict__ bias, float4* __restrict__ out)
{
    int idx = blockIdx.x * blockDim.x + threadIdx.x;
    if (idx >= M_TOK * DIM / 4) return;
    float4 a = p0[idx], b = p1[idx];
    float4 bs = bias[idx & (DIM / 4 - 1)];
    out[idx] = make_float4(a.x + b.x + bs.x, a.y + b.y + bs.y,
                           a.z + b.z + bs.z, a.w + b.w + bs.w);
}

// ---------------------------------------------------------------------------
// fp16 mma.sync GEMM: 256 thr, BM=BN=128, warp 32x64, occ 2, 3-stage cp.async,
// optional split-K via blockIdx.z.
// ---------------------------------------------------------------------------
#define STAGES 3

__device__ __forceinline__ uint32_t smem_u32(const void* p) {
    return (uint32_t)__cvta_generic_to_shared(p);
}

template<bool BIAS, typename OutT>
__global__ __launch_bounds__(256, 2)
void gemm_fp16_mma(const __half* __restrict__ A, const __half* __restrict__ B,
                   const float* __restrict__ bias, OutT* __restrict__ C,
                   int KTsplit, int KTtotal, int kbytes, int Nstore, int ldc,
                   size_t part_stride)
{
    constexpr int BMt = 128, BNt = 128, WM = 32, WN = 64;
    constexpr int STAGE_BYTES = (BMt + BNt) * 128;
    constexpr int A_BYTES     = BMt * 128;
    constexpr int NWN  = BNt / WN;
    constexpr int NI   = WM / 16;
    constexpr int NB16 = WN / 16;
    constexpr int NJ   = WN / 8;

    extern __shared__ char smem[];
    uint32_t sbase = smem_u32(smem);
    const int tid  = threadIdx.x;
    const int wid  = tid >> 5;
    const int lane = tid & 31;
    const int wm   = wid / NWN;
    const int wn   = wid % NWN;
    const int m0   = blockIdx.y * BMt;
    const int n0   = blockIdx.x * BNt;
    const int z    = blockIdx.z;
    const int kt_lo = z ? KTsplit : 0;
    const int kt_hi = z ? KTtotal : KTsplit;
    C += (size_t)z * part_stride;

    const char* Ab = (const char*)A + (size_t)m0 * kbytes;
    const char* Bb = (const char*)B + (size_t)n0 * kbytes;

    float acc[NI][NJ][4];
#pragma unroll
    for (int i = 0; i < NI; i++)
#pragma unroll
        for (int j = 0; j < NJ; j++)
#pragma unroll
            for (int q = 0; q < 4; q++) acc[i][j][q] = 0.0f;

    auto load_stage = [&](int s, int kt2) {
        uint32_t st = sbase + s * STAGE_BYTES;
        size_t koff = (size_t)kt2 * 128;
#pragma unroll
        for (int i = 0; i < BMt / 32; i++) {
            int id  = tid + i * 256;
            int row = id >> 3;
            int c   = id & 7;
            uint32_t so = (uint32_t)(row * 128 + ((c ^ (row & 7)) << 4));
            const char* ga = Ab + (size_t)row * kbytes + koff + ((size_t)c << 4);
            asm volatile("cp.async.cg.shared.global [%0], [%1], 16;" :: "r"(st + so), "l"(ga) : "memory");
        }
#pragma unroll
        for (int i = 0; i < BNt / 32; i++) {
            int id  = tid + i * 256;
            int row = id >> 3;
            int c   = id & 7;
            uint32_t so = (uint32_t)(row * 128 + ((c ^ (row & 7)) << 4));
            const char* gb = Bb + (size_t)row * kbytes + koff + ((size_t)c << 4);
            asm volatile("cp.async.cg.shared.global [%0], [%1], 16;" :: "r"(st + A_BYTES + so), "l"(gb) : "memory");
        }
        asm volatile("cp.async.commit_group;" ::: "memory");
    };

    const int lrow = lane & 15;
    const int lch  = lane >> 4;
    uint32_t offA[NI], offB[NB16];
#pragma unroll
    for (int i = 0; i < NI; i++) {
        int r = wm * WM + i * 16 + lrow;
        offA[i] = (uint32_t)(r * 128 + ((lch ^ (r & 7)) << 4));
    }
#pragma unroll
    for (int j = 0; j < NB16; j++) {
        int r = wn * WN + j * 16 + lrow;
        offB[j] = (uint32_t)(A_BYTES + r * 128 + ((lch ^ (r & 7)) << 4));
    }

#pragma unroll
    for (int p = 0; p < STAGES - 1; p++) load_stage(p, kt_lo + p);

    for (int kt = kt_lo; kt < kt_hi; kt++) {
        int s = (kt - kt_lo) % STAGES;
        asm volatile("cp.async.wait_group 1;" ::: "memory");
        __syncthreads();

        int ktn = kt + STAGES - 1;
        if (ktn < kt_hi) load_stage((ktn - kt_lo) % STAGES, ktn);
        else             asm volatile("cp.async.commit_group;" ::: "memory");

        uint32_t sA = sbase + s * STAGE_BYTES;

#pragma unroll
        for (int k16 = 0; k16 < 4; k16++) {
            const uint32_t kx = (uint32_t)(k16 << 5);
            uint32_t a[NI][4], b[NB16][4];
#pragma unroll
            for (int i = 0; i < NI; i++) {
                asm volatile("ldmatrix.sync.aligned.m8n8.x4.shared.b16 {%0,%1,%2,%3}, [%4];"
                             : "=r"(a[i][0]), "=r"(a[i][1]), "=r"(a[i][2]), "=r"(a[i][3])
                             : "r"(sA + (offA[i] ^ kx)));
            }
#pragma unroll
            for (int j = 0; j < NB16; j++) {
                asm volatile("ldmatrix.sync.aligned.m8n8.x4.shared.b16 {%0,%1,%2,%3}, [%4];"
                             : "=r"(b[j][0]), "=r"(b[j][1]), "=r"(b[j][2]), "=r"(b[j][3])
                             : "r"(sA + (offB[j] ^ kx)));
            }
#pragma unroll
            for (int i = 0; i < NI; i++) {
#pragma unroll
                for (int jn = 0; jn < NJ; jn++) {
                    int jj = jn >> 1;
                    uint32_t b0 = (jn & 1) ? b[jj][1] : b[jj][0];
                    uint32_t b1 = (jn & 1) ? b[jj][3] : b[jj][2];
                    asm volatile(
                        "mma.sync.aligned.m16n8k16.row.col.f32.f16.f16.f32 "
                        "{%0,%1,%2,%3}, {%4,%5,%6,%7}, {%8,%9}, {%0,%1,%2,%3};"
                        : "+f"(acc[i][jn][0]), "+f"(acc[i][jn][1]),
                          "+f"(acc[i][jn][2]), "+f"(acc[i][jn][3])
                        : "r"(a[i][0]), "r"(a[i][1]), "r"(a[i][2]), "r"(a[i][3]),
                          "r"(b0), "r"(b1));
                }
            }
        }
    }

    const int g  = lane >> 2;
    const int tg = lane & 3;
#pragma unroll
    for (int i = 0; i < NI; i++) {
        int r0 = m0 + wm * WM + i * 16 + g;
#pragma unroll
        for (int jn = 0; jn < NJ; jn++) {
            int col = n0 + wn * WN + jn * 8 + tg * 2;
            if (col < Nstore) {
                float bx = BIAS ? bias[col]     : 0.0f;
                float by = BIAS ? bias[col + 1] : 0.0f;
                float c00 = acc[i][jn][0] + bx, c01 = acc[i][jn][1] + by;
                float c10 = acc[i][jn][2] + bx, c11 = acc[i][jn][3] + by;
                if constexpr (sizeof(OutT) == 2) {
                    *reinterpret_cast<__half2*>((__half*)C + (size_t)r0       * ldc + col) = __floats2half2_rn(c00, c01);
                    *reinterpret_cast<__half2*>((__half*)C + (size_t)(r0 + 8) * ldc + col) = __floats2half2_rn(c10, c11);
                } else {
                    *reinterpret_cast<float2*>((float*)C + (size_t)r0       * ldc + col) = make_float2(c00, c01);
                    *reinterpret_cast<float2*>((float*)C + (size_t)(r0 + 8) * ldc + col) = make_float2(c10, c11);
                }
            }
        }
    }
}

// ---------------------------------------------------------------------------
extern "C" void kernel_launch(void* const* d_in, const int* in_sizes, int n_in,
                              void* d_out, int out_size)
{
    const float* x  = (const float*)d_in[0];
    const float* W1 = (const float*)d_in[1];
    const float* b1 = (const float*)d_in[2];
    const float* W2 = (const float*)d_in[3];
    const float* b2 = (const float*)d_in[4];
    float* out = (float*)d_out;

    __half *h_ptr, *pix_ptr, *A1, *B1, *A2, *B2;
    float *part_ptr, *b1p_ptr;
    cudaGetSymbolAddress((void**)&h_ptr,   g_h);
    cudaGetSymbolAddress((void**)&pix_ptr, g_pix);
    cudaGetSymbolAddress((void**)&A1, g_A1);
    cudaGetSymbolAddress((void**)&B1, g_B1);
    cudaGetSymbolAddress((void**)&A2, g_A2);
    cudaGetSymbolAddress((void**)&B2, g_B2);
    cudaGetSymbolAddress((void**)&part_ptr, g_part);
    cudaGetSymbolAddress((void**)&b1p_ptr,  g_b1p);

    constexpr int GSMEM = STAGES * 256 * 128;   // 98304, occ 2
    cudaFuncSetAttribute((const void*)gemm_fp16_mma<true, __half>,
                         cudaFuncAttributeMaxDynamicSharedMemorySize, GSMEM);
    cudaFuncSetAttribute((const void*)gemm_fp16_mma<false, float>,
                         cudaFuncAttributeMaxDynamicSharedMemorySize, GSMEM);

    // merged operand prep (1 launch)
    prep_all_kernel<<<NB_ALL, 256>>>((const float4*)x, (__half2*)A1,
                                     W1, B1, b1, b1p_ptr, W2, (__half2*)B2);

    // GEMM1 (permuted N): g_h = x @ B1^T + b1p
    {
        dim3 grid(N1PAD / 128, M_TOK / 128, 1);
        gemm_fp16_mma<true, __half><<<grid, 256, GSMEM>>>(
            A1, B1, b1p_ptr, h_ptr, DIM / 64, DIM / 64, DIM * 2, HID, HID, 0);
    }
    // fold + normalize + GELU (channel-last, half2)
    {
        int n = NPIX / 2;
        fold_div_kernel<<<(n + 255) / 256, 256>>>(h_ptr, (__half2*)pix_ptr);
    }
    // unfold -> A2 (pure int4 gather)
    {
        int n = M_TOK * CPT;
        prep_A2_kernel<<<(n + 255) / 256, 256>>>(pix_ptr, (int4*)A2);
    }
    // GEMM2 split-K partials
    {
        dim3 grid(DIM / 128, M_TOK / 128, 2);
        gemm_fp16_mma<false, float><<<grid, 256, GSMEM>>>(
            A2, B2, nullptr, part_ptr, 960 / 64, K2PAD / 64, K2PAD * 2, DIM, DIM,
            (size_t)M_TOK * DIM);
    }
    // combine
    {
        int n = M_TOK * DIM / 4;
        combine_kernel<<<(n + 255) / 256, 256>>>(
            (const float4*)part_ptr, (const float4*)(part_ptr + (size_t)M_TOK * DIM),
            (const float4*)b2, (float4*)out);
    }
}